// round 4
// baseline (speedup 1.0000x reference)
#include <cuda_runtime.h>
#include <math.h>

#define NA 128        // atoms
#define NB 2          // batch
#define EE 512        // embed
#define HH 1024       // hidden
#define GG 50         // gaussians
#define MROWS (NA*NA*NB)   // 32768 pair rows

// -------- device scratch (no allocations allowed) --------
__device__ float d_hA[(size_t)MROWS*HH];   // 128 MiB
__device__ float d_hB[(size_t)MROWS*HH];   // 128 MiB
__device__ float d_g[(size_t)MROWS*GG];    // RBF features
__device__ float d_P[NA*NB*HH];            // x @ Win[0:512]
__device__ float d_Q[NA*NB*HH];            // x @ Win[512:1024]
__device__ float d_Wg[GG*HH];              // rbf_W @ Win[1024:1536]
__device__ float d_b0[HH];                 // bin + rbf_b @ Win3
__device__ float d_eP[NA*NB];              // per-(j,b) energy partials

__device__ __forceinline__ float gelu_exact(float x) {
    return x * normcdff(x);   // x * 0.5*(1+erf(x/sqrt(2)))
}

// -------- kernel 1: RBF expansion g[m][k] = exp(coeff*(d_m - off_k)^2) --------
__global__ void rbf_kernel(const float* __restrict__ dist) {
    int idx = blockIdx.x * blockDim.x + threadIdx.x;
    if (idx >= MROWS * GG) return;
    int m = idx / GG;
    int k = idx - m * GG;
    const float delta = 12.0f / 49.0f;
    const float coeff = -0.5f / (delta * delta);
    float t = dist[m] - delta * (float)k;
    d_g[idx] = expf(coeff * t * t);
}

// -------- kernel 2: fold bin + rbf_b @ Win3 into bias0 --------
__global__ void bias0_kernel(const float* __restrict__ Win3,
                             const float* __restrict__ bin,
                             const float* __restrict__ rbf_b) {
    int h = blockIdx.x * blockDim.x + threadIdx.x;
    if (h >= HH) return;
    float s = bin[h];
    for (int e = 0; e < EE; e++) s += rbf_b[e] * Win3[(size_t)e * HH + h];
    d_b0[h] = s;
}

// -------- generic fp32 SGEMM: out = epilogue(A[M,K] @ W[K,N] + bias) --------
// mode 0: out = acc + bias        (bias may be null)
// mode 2: out = res + gelu(acc + bias)   (residual layer)
#define BM 128
#define BN 128
#define BK 16
__global__ __launch_bounds__(256)
void sgemm_kernel(const float* __restrict__ A, const float* __restrict__ W,
                  const float* __restrict__ bias, const float* __restrict__ res,
                  float* __restrict__ out, int M, int N, int K, int mode)
{
    __shared__ float As[BK][BM];
    __shared__ float Bs[BK][BN];
    int tid = threadIdx.x;
    int tx = tid & 15, ty = tid >> 4;
    int bm = blockIdx.x * BM, bn = blockIdx.y * BN;

    float acc[8][8] = {};

    int arow = tid >> 2;           // 0..63  (two rows: arow, arow+64)
    int acol = (tid & 3) * 4;      // 0,4,8,12
    int brow = tid >> 5;           // 0..7   (two rows: brow, brow+8)
    int bcol = (tid & 31) * 4;

    // ---- prefetch tile 0 into registers ----
    float4 ra[2], rb[2];
    #pragma unroll
    for (int h = 0; h < 2; h++) {
        int r = arow + h * 64;
        ra[h] = make_float4(0.f, 0.f, 0.f, 0.f);
        if (bm + r < M)
            ra[h] = *(const float4*)(A + (size_t)(bm + r) * K + acol);
        rb[h] = *(const float4*)(W + (size_t)(brow + h * 8) * N + bn + bcol);
    }

    for (int k0 = 0; k0 < K; k0 += BK) {
        // store current tile to smem
        #pragma unroll
        for (int h = 0; h < 2; h++) {
            int r = arow + h * 64;
            As[acol + 0][r] = ra[h].x; As[acol + 1][r] = ra[h].y;
            As[acol + 2][r] = ra[h].z; As[acol + 3][r] = ra[h].w;
            *(float4*)&Bs[brow + h * 8][bcol] = rb[h];
        }
        __syncthreads();

        // prefetch next tile (overlaps with compute below)
        if (k0 + BK < K) {
            #pragma unroll
            for (int h = 0; h < 2; h++) {
                int r = arow + h * 64;
                ra[h] = make_float4(0.f, 0.f, 0.f, 0.f);
                if (bm + r < M)
                    ra[h] = *(const float4*)(A + (size_t)(bm + r) * K + k0 + BK + acol);
                rb[h] = *(const float4*)(W + (size_t)(k0 + BK + brow + h * 8) * N + bn + bcol);
            }
        }

        #pragma unroll
        for (int kk = 0; kk < BK; kk++) {
            float a[8], b[8];
            #pragma unroll
            for (int i = 0; i < 8; i++) a[i] = As[kk][ty * 8 + i];
            #pragma unroll
            for (int j = 0; j < 8; j++) b[j] = Bs[kk][tx * 8 + j];
            #pragma unroll
            for (int i = 0; i < 8; i++)
                #pragma unroll
                for (int j = 0; j < 8; j++)
                    acc[i][j] = fmaf(a[i], b[j], acc[i][j]);
        }
        __syncthreads();
    }

    #pragma unroll
    for (int i = 0; i < 8; i++) {
        int row = bm + ty * 8 + i;
        if (row < M) {
            #pragma unroll
            for (int j = 0; j < 8; j++) {
                int col = bn + tx * 8 + j;
                float v = acc[i][j] + (bias ? bias[col] : 0.0f);
                if (mode == 2) v = res[(size_t)row * N + col] + gelu_exact(v);
                out[(size_t)row * N + col] = v;
            }
        }
    }
}

// -------- h0: out = gelu(g@Wg + P[i,b] + Q[j,b] + bias0) --------
__global__ __launch_bounds__(256)
void h0_kernel(float* __restrict__ out)
{
    __shared__ float Gs[64][52];
    __shared__ float Ws[52][64];
    int tid = threadIdx.x;
    int bm = blockIdx.x * 64, bn = blockIdx.y * 64;

    for (int idx = tid; idx < 64 * GG; idx += 256) {
        int r = idx / GG, k = idx - r * GG;
        Gs[r][k] = d_g[(size_t)(bm + r) * GG + k];
    }
    for (int idx = tid; idx < GG * 64; idx += 256) {
        int k = idx >> 6, n = idx & 63;
        Ws[k][n] = d_Wg[k * HH + bn + n];
    }
    __syncthreads();

    int tx = tid & 15, ty = tid >> 4;
    float acc[4][4] = {};
    #pragma unroll 10
    for (int k = 0; k < GG; k++) {
        float a[4], b[4];
        #pragma unroll
        for (int i = 0; i < 4; i++) a[i] = Gs[ty * 4 + i][k];
        #pragma unroll
        for (int j = 0; j < 4; j++) b[j] = Ws[k][tx * 4 + j];
        #pragma unroll
        for (int i = 0; i < 4; i++)
            #pragma unroll
            for (int j = 0; j < 4; j++)
                acc[i][j] = fmaf(a[i], b[j], acc[i][j]);
    }
    #pragma unroll
    for (int i = 0; i < 4; i++) {
        int m = bm + ty * 4 + i;
        int bb  = m & (NB - 1);
        int jat = (m / NB) & (NA - 1);
        int iat = m / (NB * NA);
        #pragma unroll
        for (int j = 0; j < 4; j++) {
            int col = bn + tx * 4 + j;
            float v = acc[i][j]
                    + d_P[(iat * NB + bb) * HH + col]
                    + d_Q[(jat * NB + bb) * HH + col]
                    + d_b0[col];
            out[(size_t)m * HH + col] = gelu_exact(v);
        }
    }
}

// -------- reduction: per (j,b) CTA, dot each row with Wout, deterministic tree --------
// NOTE: mask is int32 on device (bool gets promoted by the harness).
// mode 0: write d_eP[(j,b)] = sum_i e_pair * entry
// mode 1: write forces out[2 + (b*NA+j)*3 + c] = sum_i f_pair*vec_hat*entry / 60
__global__ __launch_bounds__(256)
void reduce_kernel(const float* __restrict__ h, const float* __restrict__ Wout,
                   const float* __restrict__ bout,
                   const int* __restrict__ mask,
                   const float* __restrict__ vec_hat,
                   float* __restrict__ out, int mode)
{
    __shared__ float sW[HH];
    __shared__ float sred[8][4];
    int tid = threadIdx.x;
    int jb = blockIdx.x;
    int j = jb / NB, b = jb % NB;
    for (int c = tid; c < HH; c += 256) sW[c] = Wout[c];
    __syncthreads();

    int warp = tid >> 5, lane = tid & 31;
    float eacc = 0.f, fx = 0.f, fy = 0.f, fz = 0.f;
    float bo = bout[0];
    bool mj = mask[b * NA + j] != 0;

    for (int i = warp; i < NA; i += 8) {
        size_t m = ((size_t)(i * NA + j)) * NB + b;
        const float* hr = h + m * HH;
        float s = 0.f;
        for (int c = lane; c < HH; c += 32) s += hr[c] * sW[c];
        #pragma unroll
        for (int o = 16; o > 0; o >>= 1) s += __shfl_xor_sync(0xffffffffu, s, o);
        if (lane == 0) {
            float entry = (mj && mask[b * NA + i] != 0) ? 1.0f : 0.0f;
            float val = (s + bo) * entry;
            if (mode == 0) {
                eacc += val;
            } else {
                const float* v = vec_hat + m * 3;
                fx += val * v[0]; fy += val * v[1]; fz += val * v[2];
            }
        }
    }
    if (lane == 0) { sred[warp][0] = eacc; sred[warp][1] = fx;
                     sred[warp][2] = fy;   sred[warp][3] = fz; }
    __syncthreads();
    if (tid == 0) {
        float a0 = 0, a1 = 0, a2 = 0, a3 = 0;
        for (int w = 0; w < 8; w++) {
            a0 += sred[w][0]; a1 += sred[w][1];
            a2 += sred[w][2]; a3 += sred[w][3];
        }
        if (mode == 0) {
            d_eP[jb] = a0;
        } else {
            int o = 2 + (b * NA + j) * 3;
            out[o + 0] = a1 / 60.0f;
            out[o + 1] = a2 / 60.0f;
            out[o + 2] = a3 / 60.0f;
        }
    }
}

// -------- final energy over j --------
__global__ void energy_kernel(float* __restrict__ out) {
    int tid = threadIdx.x;
    int b = tid >> 5, lane = tid & 31;
    if (b >= NB) return;
    float s = 0.f;
    for (int j = lane; j < NA; j += 32) s += d_eP[j * NB + b];
    #pragma unroll
    for (int o = 16; o > 0; o >>= 1) s += __shfl_xor_sync(0xffffffffu, s, o);
    if (lane == 0) out[b] = s / 3600.0f;
}

// -------- launch --------
extern "C" void kernel_launch(void* const* d_in, const int* in_sizes, int n_in,
                              void* d_out, int out_size)
{
    const float* x       = (const float*)d_in[0];
    const float* dist    = (const float*)d_in[1];
    const float* vec_hat = (const float*)d_in[2];
    const int*   mask    = (const int*)d_in[3];   // bool promoted to int32
    const float* rbf_W   = (const float*)d_in[4];
    const float* rbf_b   = (const float*)d_in[5];
    const float* Win[2]  = {(const float*)d_in[6],  (const float*)d_in[12]};
    const float* bin[2]  = {(const float*)d_in[7],  (const float*)d_in[13]};
    const float* Wh[2]   = {(const float*)d_in[8],  (const float*)d_in[14]};
    const float* bh[2]   = {(const float*)d_in[9],  (const float*)d_in[15]};
    const float* Wout[2] = {(const float*)d_in[10], (const float*)d_in[16]};
    const float* bout[2] = {(const float*)d_in[11], (const float*)d_in[17]};
    int L = in_sizes[8] / (HH * HH);
    float* out = (float*)d_out;

    float *hA, *hB, *P, *Q, *Wg;
    cudaGetSymbolAddress((void**)&hA, d_hA);
    cudaGetSymbolAddress((void**)&hB, d_hB);
    cudaGetSymbolAddress((void**)&P,  d_P);
    cudaGetSymbolAddress((void**)&Q,  d_Q);
    cudaGetSymbolAddress((void**)&Wg, d_Wg);

    rbf_kernel<<<(MROWS * GG + 255) / 256, 256>>>(dist);

    for (int mlp = 0; mlp < 2; mlp++) {
        const float* W1 = Win[mlp];
        const float* W2 = Win[mlp] + (size_t)EE * HH;
        const float* W3 = Win[mlp] + (size_t)2 * EE * HH;

        sgemm_kernel<<<dim3(2, 8), 256>>>(x, W1, nullptr, nullptr, P, NA * NB, HH, EE, 0);
        sgemm_kernel<<<dim3(2, 8), 256>>>(x, W2, nullptr, nullptr, Q, NA * NB, HH, EE, 0);
        sgemm_kernel<<<dim3(1, 8), 256>>>(rbf_W, W3, nullptr, nullptr, Wg, GG, HH, EE, 0);
        bias0_kernel<<<4, 256>>>(W3, bin[mlp], rbf_b);

        h0_kernel<<<dim3(MROWS / 64, HH / 64), 256>>>(hA);

        float* cur = hA; float* nxt = hB;
        for (int l = 0; l < L; l++) {
            sgemm_kernel<<<dim3(MROWS / 128, HH / 128), 256>>>(
                cur, Wh[mlp] + (size_t)l * HH * HH, bh[mlp] + (size_t)l * HH,
                cur, nxt, MROWS, HH, HH, 2);
            float* t = cur; cur = nxt; nxt = t;
        }

        reduce_kernel<<<NA * NB, 256>>>(cur, Wout[mlp], bout[mlp],
                                        mask, vec_hat, out, mlp);
    }

    energy_kernel<<<1, 64>>>(out);
}

// round 7
// speedup vs baseline: 2.3357x; 2.3357x over previous
#include <cuda_runtime.h>
#include <cuda_bf16.h>
#include <math.h>

#define NA 128
#define NB 2
#define EE 512
#define HH 1024
#define GG 50
#define MROWS (NA*NA*NB)          // 32768
#define AW ((size_t)MROWS*HH/2)   // u32 words per bf16 activation array
#define WW ((size_t)HH*HH/2)      // u32 words per bf16 weight matrix

// -------- device scratch (no allocations allowed) --------
__device__ float d_hA[(size_t)MROWS*HH];
__device__ float d_hB[(size_t)MROWS*HH];
__device__ float d_g[(size_t)MROWS*GG];
__device__ float d_P[NA*NB*HH];
__device__ float d_Q[NA*NB*HH];
__device__ float d_Wg[GG*HH];
__device__ float d_b0[HH];
__device__ float d_eP[NA*NB];
__device__ unsigned d_bfHiA[AW];
__device__ unsigned d_bfLoA[AW];
__device__ unsigned d_bfHiB[AW];
__device__ unsigned d_bfLoB[AW];
__device__ unsigned d_WtHi[6*WW];
__device__ unsigned d_WtLo[6*WW];

__device__ __forceinline__ float gelu_exact(float x) { return x * normcdff(x); }

__device__ __forceinline__ unsigned smem_u32(const void* p) {
    unsigned a;
    asm("{ .reg .u64 t; cvta.to.shared.u64 t, %1; cvt.u32.u64 %0, t; }" : "=r"(a) : "l"(p));
    return a;
}
__device__ __forceinline__ void ldsm4(unsigned addr, unsigned* r) {
    asm volatile("ldmatrix.sync.aligned.m8n8.x4.shared.b16 {%0,%1,%2,%3}, [%4];"
                 : "=r"(r[0]), "=r"(r[1]), "=r"(r[2]), "=r"(r[3]) : "r"(addr));
}
__device__ __forceinline__ void mma16816(float* c, const unsigned* a, unsigned b0, unsigned b1) {
    asm volatile("mma.sync.aligned.m16n8k16.row.col.f32.bf16.bf16.f32 "
                 "{%0,%1,%2,%3}, {%4,%5,%6,%7}, {%8,%9}, {%0,%1,%2,%3};"
                 : "+f"(c[0]), "+f"(c[1]), "+f"(c[2]), "+f"(c[3])
                 : "r"(a[0]), "r"(a[1]), "r"(a[2]), "r"(a[3]), "r"(b0), "r"(b1));
}
__device__ __forceinline__ unsigned pack_hi(float v0, float v1, float& l0, float& l1) {
    __nv_bfloat16 b0 = __float2bfloat16(v0), b1 = __float2bfloat16(v1);
    l0 = v0 - __bfloat162float(b0);
    l1 = v1 - __bfloat162float(b1);
    return ((unsigned)__bfloat16_as_ushort(b1) << 16) | __bfloat16_as_ushort(b0);
}
__device__ __forceinline__ unsigned pack_lo(float l0, float l1) {
    return ((unsigned)__bfloat16_as_ushort(__float2bfloat16(l1)) << 16)
         | __bfloat16_as_ushort(__float2bfloat16(l0));
}

// ================= small kernels (R4-passing fp32 path) =================
__global__ void rbf_kernel(const float* __restrict__ dist) {
    int idx = blockIdx.x * blockDim.x + threadIdx.x;
    if (idx >= MROWS * GG) return;
    int m = idx / GG, k = idx - m * GG;
    const float delta = 12.0f / 49.0f;
    const float coeff = -0.5f / (delta * delta);
    float t = dist[m] - delta * (float)k;
    d_g[idx] = expf(coeff * t * t);
}

__global__ void bias0_kernel(const float* __restrict__ Win3,
                             const float* __restrict__ bin,
                             const float* __restrict__ rbf_b) {
    int h = blockIdx.x * blockDim.x + threadIdx.x;
    if (h >= HH) return;
    float s = bin[h];
    for (int e = 0; e < EE; e++) s += rbf_b[e] * Win3[(size_t)e * HH + h];
    d_b0[h] = s;
}

#define BM 128
#define BN 128
#define BK 16
__global__ __launch_bounds__(256)
void sgemm_kernel(const float* __restrict__ A, const float* __restrict__ W,
                  float* __restrict__ out, int M, int N, int K)
{
    __shared__ float As[BK][BM];
    __shared__ float Bs[BK][BN];
    int tid = threadIdx.x;
    int tx = tid & 15, ty = tid >> 4;
    int bm = blockIdx.x * BM, bn = blockIdx.y * BN;
    float acc[8][8] = {};
    int arow = tid >> 2, acol = (tid & 3) * 4;
    int brow = tid >> 5, bcol = (tid & 31) * 4;
    float4 ra[2], rb[2];
    #pragma unroll
    for (int h = 0; h < 2; h++) {
        int r = arow + h * 64;
        ra[h] = make_float4(0.f, 0.f, 0.f, 0.f);
        if (bm + r < M) ra[h] = *(const float4*)(A + (size_t)(bm + r) * K + acol);
        rb[h] = *(const float4*)(W + (size_t)(brow + h * 8) * N + bn + bcol);
    }
    for (int k0 = 0; k0 < K; k0 += BK) {
        #pragma unroll
        for (int h = 0; h < 2; h++) {
            int r = arow + h * 64;
            As[acol + 0][r] = ra[h].x; As[acol + 1][r] = ra[h].y;
            As[acol + 2][r] = ra[h].z; As[acol + 3][r] = ra[h].w;
            *(float4*)&Bs[brow + h * 8][bcol] = rb[h];
        }
        __syncthreads();
        if (k0 + BK < K) {
            #pragma unroll
            for (int h = 0; h < 2; h++) {
                int r = arow + h * 64;
                ra[h] = make_float4(0.f, 0.f, 0.f, 0.f);
                if (bm + r < M) ra[h] = *(const float4*)(A + (size_t)(bm + r) * K + k0 + BK + acol);
                rb[h] = *(const float4*)(W + (size_t)(k0 + BK + brow + h * 8) * N + bn + bcol);
            }
        }
        #pragma unroll
        for (int kk = 0; kk < BK; kk++) {
            float a[8], b[8];
            #pragma unroll
            for (int i = 0; i < 8; i++) a[i] = As[kk][ty * 8 + i];
            #pragma unroll
            for (int j = 0; j < 8; j++) b[j] = Bs[kk][tx * 8 + j];
            #pragma unroll
            for (int i = 0; i < 8; i++)
                #pragma unroll
                for (int j = 0; j < 8; j++)
                    acc[i][j] = fmaf(a[i], b[j], acc[i][j]);
        }
        __syncthreads();
    }
    #pragma unroll
    for (int i = 0; i < 8; i++) {
        int row = bm + ty * 8 + i;
        if (row < M)
            #pragma unroll
            for (int j = 0; j < 8; j++)
                out[(size_t)row * N + bn + tx * 8 + j] = acc[i][j];
    }
}

__global__ __launch_bounds__(256)
void h0_kernel(float* __restrict__ out)
{
    __shared__ float Gs[64][52];
    __shared__ float Ws[52][64];
    int tid = threadIdx.x;
    int bm = blockIdx.x * 64, bn = blockIdx.y * 64;
    for (int idx = tid; idx < 64 * GG; idx += 256) {
        int r = idx / GG, k = idx - r * GG;
        Gs[r][k] = d_g[(size_t)(bm + r) * GG + k];
    }
    for (int idx = tid; idx < GG * 64; idx += 256) {
        int k = idx >> 6, n = idx & 63;
        Ws[k][n] = d_Wg[k * HH + bn + n];
    }
    __syncthreads();
    int tx = tid & 15, ty = tid >> 4;
    float acc[4][4] = {};
    #pragma unroll 10
    for (int k = 0; k < GG; k++) {
        float a[4], b[4];
        #pragma unroll
        for (int i = 0; i < 4; i++) a[i] = Gs[ty * 4 + i][k];
        #pragma unroll
        for (int j = 0; j < 4; j++) b[j] = Ws[k][tx * 4 + j];
        #pragma unroll
        for (int i = 0; i < 4; i++)
            #pragma unroll
            for (int j = 0; j < 4; j++)
                acc[i][j] = fmaf(a[i], b[j], acc[i][j]);
    }
    #pragma unroll
    for (int i = 0; i < 4; i++) {
        int m = bm + ty * 4 + i;
        int bb = m & (NB - 1);
        int jat = (m / NB) & (NA - 1);
        int iat = m / (NB * NA);
        #pragma unroll
        for (int j = 0; j < 4; j++) {
            int col = bn + tx * 4 + j;
            float v = acc[i][j] + d_P[(iat * NB + bb) * HH + col]
                    + d_Q[(jat * NB + bb) * HH + col] + d_b0[col];
            out[(size_t)m * HH + col] = gelu_exact(v);
        }
    }
}

// ========= split fp32 h[M][HH] -> bf16 hi/lo packed u32 [M][HH/2] =========
__global__ void split_kernel(const float* __restrict__ h,
                             unsigned* __restrict__ hi, unsigned* __restrict__ lo)
{
    for (size_t w = (size_t)blockIdx.x * 256 + threadIdx.x; w < AW;
         w += (size_t)gridDim.x * 256) {
        float2 v = *(const float2*)(h + w * 2);
        float l0, l1;
        hi[w] = pack_hi(v.x, v.y, l0, l1);
        lo[w] = pack_lo(l0, l1);
    }
}

// ========= weight prep: W[K][N] fp32 -> Wt[N][K] bf16 hi/lo (u32 k-pairs) =========
__global__ __launch_bounds__(256)
void prep_w(const float* __restrict__ We, const float* __restrict__ Wf,
            unsigned* __restrict__ hi, unsigned* __restrict__ lo)
{
    __shared__ float ts[64][33];
    int z = blockIdx.z;
    const float* W = (z < 3) ? We + (size_t)z * HH * HH : Wf + (size_t)(z - 3) * HH * HH;
    int k0 = blockIdx.x * 64, n0 = blockIdx.y * 32;
    int tid = threadIdx.x;
    #pragma unroll
    for (int i = 0; i < 8; i++) {
        int r = (tid >> 5) + i * 8, c = tid & 31;
        ts[r][c] = W[(size_t)(k0 + r) * HH + n0 + c];
    }
    __syncthreads();
    size_t zo = (size_t)z * WW;
    #pragma unroll
    for (int i = 0; i < 4; i++) {
        int on = (tid >> 5) + i * 8;
        int ok = tid & 31;
        float v0 = ts[ok * 2][on], v1 = ts[ok * 2 + 1][on];
        float l0, l1;
        unsigned hw = pack_hi(v0, v1, l0, l1);
        size_t oidx = zo + (size_t)(n0 + on) * (HH / 2) + (k0 >> 1) + ok;
        hi[oidx] = hw;
        lo[oidx] = pack_lo(l0, l1);
    }
}

// ========= bf16x3 mma.sync GEMM layer: out = res + gelu(A@W^T + bias) =========
// A: [M][HH] bf16 hi/lo (u32 pairs), Wt: [HH][HH] n-major bf16 hi/lo
// CTA tile 128x128, BK=64, 8 warps (4m x 2n), warp tile 32x64, m16n8k16
#define SMSTR 144                  // smem row stride bytes (72 bf16, +8 pad)
#define TILEB (128*SMSTR)          // 18432 bytes per tile
#define DSMEM_BYTES (4*TILEB)      // 73728

__global__ __launch_bounds__(256, 2)
void mma_layer(const uint4* __restrict__ Ah, const uint4* __restrict__ Al,
               const uint4* __restrict__ Bh, const uint4* __restrict__ Bl,
               const float* __restrict__ bias, const float* __restrict__ res,
               float* __restrict__ outf,
               unsigned* __restrict__ oHi, unsigned* __restrict__ oLo, int writeSplit)
{
    extern __shared__ char dsm[];
    __shared__ float s_bias[128];
    char* pAh = dsm;
    char* pAl = dsm + TILEB;
    char* pBh = dsm + 2 * TILEB;
    char* pBl = dsm + 3 * TILEB;
    unsigned base = smem_u32(dsm);

    int tid = threadIdx.x;
    int nt_blk = blockIdx.x, mt_blk = blockIdx.y;
    if (tid < 128) s_bias[tid] = bias[nt_blk * 128 + tid];

    int wid = tid >> 5, lane = tid & 31;
    int wm = wid & 3, wn = wid >> 2;

    float acc[2][8][4];
    #pragma unroll
    for (int i = 0; i < 2; i++)
        #pragma unroll
        for (int j = 0; j < 8; j++)
            #pragma unroll
            for (int k = 0; k < 4; k++) acc[i][j][k] = 0.f;

    const uint4* gAh = Ah + (size_t)(mt_blk * 128) * 128;   // 128 uint4 per row
    const uint4* gAl = Al + (size_t)(mt_blk * 128) * 128;
    const uint4* gBh = Bh + (size_t)(nt_blk * 128) * 128;
    const uint4* gBl = Bl + (size_t)(nt_blk * 128) * 128;

    // ldmatrix lane-address components
    int g = lane >> 3, lr = lane & 7;
    unsigned aoff0 = (unsigned)((wm * 32 + (g & 1) * 8 + lr) * SMSTR + ((g >> 1) * 8) * 2);
    unsigned boff0 = (unsigned)((wn * 64 + (g >> 1) * 8 + lr) * SMSTR + ((g & 1) * 8) * 2);

    for (int kc = 0; kc < 16; kc++) {
        __syncthreads();
        #pragma unroll
        for (int i = 0; i < 4; i++) {
            int idx = tid + i * 256;
            int row = idx >> 3, seg = idx & 7;
            size_t src = (size_t)row * 128 + kc * 8 + seg;
            unsigned doff = row * SMSTR + seg * 16;
            *(uint4*)(pAh + doff) = gAh[src];
            *(uint4*)(pAl + doff) = gAl[src];
            *(uint4*)(pBh + doff) = gBh[src];
            *(uint4*)(pBl + doff) = gBl[src];
        }
        __syncthreads();

        #pragma unroll
        for (int ks = 0; ks < 4; ks++) {
            unsigned kkb = ks * 32;   // 16 bf16 = 32 bytes
            unsigned ah[2][4], al[2][4], b[4][4];
            #pragma unroll
            for (int mt = 0; mt < 2; mt++) {
                unsigned ao = aoff0 + kkb + mt * (16 * SMSTR);
                ldsm4(base + ao, ah[mt]);
                ldsm4(base + TILEB + ao, al[mt]);
            }
            #pragma unroll
            for (int p = 0; p < 4; p++)
                ldsm4(base + 2 * TILEB + boff0 + kkb + p * (16 * SMSTR), b[p]);
            #pragma unroll
            for (int mt = 0; mt < 2; mt++)
                #pragma unroll
                for (int nt = 0; nt < 8; nt++)
                    mma16816(acc[mt][nt], ah[mt], b[nt >> 1][(nt & 1) * 2], b[nt >> 1][(nt & 1) * 2 + 1]);
            #pragma unroll
            for (int mt = 0; mt < 2; mt++)
                #pragma unroll
                for (int nt = 0; nt < 8; nt++)
                    mma16816(acc[mt][nt], al[mt], b[nt >> 1][(nt & 1) * 2], b[nt >> 1][(nt & 1) * 2 + 1]);
            #pragma unroll
            for (int p = 0; p < 4; p++)
                ldsm4(base + 3 * TILEB + boff0 + kkb + p * (16 * SMSTR), b[p]);
            #pragma unroll
            for (int mt = 0; mt < 2; mt++)
                #pragma unroll
                for (int nt = 0; nt < 8; nt++)
                    mma16816(acc[mt][nt], ah[mt], b[nt >> 1][(nt & 1) * 2], b[nt >> 1][(nt & 1) * 2 + 1]);
        }
    }

    // epilogue
    #pragma unroll
    for (int mt = 0; mt < 2; mt++) {
        #pragma unroll
        for (int half = 0; half < 2; half++) {
            int row = mt_blk * 128 + wm * 32 + mt * 16 + half * 8 + (lane >> 2);
            #pragma unroll
            for (int nt = 0; nt < 8; nt++) {
                int cl = wn * 64 + nt * 8 + (lane & 3) * 2;
                size_t gi = (size_t)row * HH + nt_blk * 128 + cl;
                float2 rv = *(const float2*)(res + gi);
                float v0 = rv.x + gelu_exact(acc[mt][nt][half * 2 + 0] + s_bias[cl]);
                float v1 = rv.y + gelu_exact(acc[mt][nt][half * 2 + 1] + s_bias[cl + 1]);
                *(float2*)(outf + gi) = make_float2(v0, v1);
                if (writeSplit) {
                    float l0, l1;
                    unsigned hw = pack_hi(v0, v1, l0, l1);
                    oHi[gi >> 1] = hw;
                    oLo[gi >> 1] = pack_lo(l0, l1);
                }
            }
        }
    }
}

// ========= reductions (fp32, deterministic) =========
__global__ __launch_bounds__(256)
void reduce_kernel(const float* __restrict__ h, const float* __restrict__ Wout,
                   const float* __restrict__ bout, const int* __restrict__ mask,
                   const float* __restrict__ vec_hat, float* __restrict__ out, int mode)
{
    __shared__ float sW[HH];
    __shared__ float sred[8][4];
    int tid = threadIdx.x;
    int jb = blockIdx.x;
    int j = jb / NB, b = jb % NB;
    for (int c = tid; c < HH; c += 256) sW[c] = Wout[c];
    __syncthreads();
    int warp = tid >> 5, lane = tid & 31;
    float eacc = 0.f, fx = 0.f, fy = 0.f, fz = 0.f;
    float bo = bout[0];
    bool mj = mask[b * NA + j] != 0;
    for (int i = warp; i < NA; i += 8) {
        size_t m = ((size_t)(i * NA + j)) * NB + b;
        const float* hr = h + m * HH;
        float s = 0.f;
        for (int c = lane; c < HH; c += 32) s += hr[c] * sW[c];
        #pragma unroll
        for (int o = 16; o > 0; o >>= 1) s += __shfl_xor_sync(0xffffffffu, s, o);
        if (lane == 0) {
            float entry = (mj && mask[b * NA + i] != 0) ? 1.0f : 0.0f;
            float val = (s + bo) * entry;
            if (mode == 0) eacc += val;
            else {
                const float* v = vec_hat + m * 3;
                fx += val * v[0]; fy += val * v[1]; fz += val * v[2];
            }
        }
    }
    if (lane == 0) { sred[warp][0] = eacc; sred[warp][1] = fx; sred[warp][2] = fy; sred[warp][3] = fz; }
    __syncthreads();
    if (tid == 0) {
        float a0 = 0, a1 = 0, a2 = 0, a3 = 0;
        for (int w = 0; w < 8; w++) { a0 += sred[w][0]; a1 += sred[w][1]; a2 += sred[w][2]; a3 += sred[w][3]; }
        if (mode == 0) d_eP[jb] = a0;
        else {
            int o = 2 + (b * NA + j) * 3;
            out[o + 0] = a1 / 60.0f; out[o + 1] = a2 / 60.0f; out[o + 2] = a3 / 60.0f;
        }
    }
}

__global__ void energy_kernel(float* __restrict__ out) {
    int tid = threadIdx.x;
    int b = tid >> 5, lane = tid & 31;
    if (b >= NB) return;
    float s = 0.f;
    for (int j = lane; j < NA; j += 32) s += d_eP[j * NB + b];
    #pragma unroll
    for (int o = 16; o > 0; o >>= 1) s += __shfl_xor_sync(0xffffffffu, s, o);
    if (lane == 0) out[b] = s / 3600.0f;
}

// ========= launch =========
extern "C" void kernel_launch(void* const* d_in, const int* in_sizes, int n_in,
                              void* d_out, int out_size)
{
    const float* x       = (const float*)d_in[0];
    const float* dist    = (const float*)d_in[1];
    const float* vec_hat = (const float*)d_in[2];
    const int*   mask    = (const int*)d_in[3];   // bool promoted to int32
    const float* rbf_W   = (const float*)d_in[4];
    const float* rbf_b   = (const float*)d_in[5];
    const float* Win[2]  = {(const float*)d_in[6],  (const float*)d_in[12]};
    const float* bin[2]  = {(const float*)d_in[7],  (const float*)d_in[13]};
    const float* Wh[2]   = {(const float*)d_in[8],  (const float*)d_in[14]};
    const float* bh[2]   = {(const float*)d_in[9],  (const float*)d_in[15]};
    const float* Wout[2] = {(const float*)d_in[10], (const float*)d_in[16]};
    const float* bout[2] = {(const float*)d_in[11], (const float*)d_in[17]};
    int L = in_sizes[8] / (HH * HH);
    float* out = (float*)d_out;

    static int attr_set = 0;
    if (!attr_set) {
        cudaFuncSetAttribute(mma_layer, cudaFuncAttributeMaxDynamicSharedMemorySize, DSMEM_BYTES);
        attr_set = 1;
    }

    float *hA, *hB;
    unsigned *bfHiA, *bfLoA, *bfHiB, *bfLoB, *WtHi, *WtLo;
    cudaGetSymbolAddress((void**)&hA, d_hA);
    cudaGetSymbolAddress((void**)&hB, d_hB);
    cudaGetSymbolAddress((void**)&bfHiA, d_bfHiA);
    cudaGetSymbolAddress((void**)&bfLoA, d_bfLoA);
    cudaGetSymbolAddress((void**)&bfHiB, d_bfHiB);
    cudaGetSymbolAddress((void**)&bfLoB, d_bfLoB);
    cudaGetSymbolAddress((void**)&WtHi, d_WtHi);
    cudaGetSymbolAddress((void**)&WtLo, d_WtLo);
    float *P, *Q, *Wg;
    cudaGetSymbolAddress((void**)&P,  d_P);
    cudaGetSymbolAddress((void**)&Q,  d_Q);
    cudaGetSymbolAddress((void**)&Wg, d_Wg);

    rbf_kernel<<<(MROWS * GG + 255) / 256, 256>>>(dist);
    prep_w<<<dim3(16, 32, 6), 256>>>(Wh[0], Wh[1], WtHi, WtLo);

    for (int mlp = 0; mlp < 2; mlp++) {
        const float* W1 = Win[mlp];
        const float* W2 = Win[mlp] + (size_t)EE * HH;
        const float* W3 = Win[mlp] + (size_t)2 * EE * HH;

        sgemm_kernel<<<dim3(2, 8), 256>>>(x, W1, P, NA * NB, HH, EE);
        sgemm_kernel<<<dim3(2, 8), 256>>>(x, W2, Q, NA * NB, HH, EE);
        sgemm_kernel<<<dim3(1, 8), 256>>>(rbf_W, W3, Wg, GG, HH, EE);
        bias0_kernel<<<4, 256>>>(W3, bin[mlp], rbf_b);

        h0_kernel<<<dim3(MROWS / 64, HH / 64), 256>>>(hA);
        split_kernel<<<8192, 256>>>(hA, bfHiA, bfLoA);

        float* curf = hA; float* nxtf = hB;
        unsigned* curHi = bfHiA; unsigned* curLo = bfLoA;
        unsigned* nxtHi = bfHiB; unsigned* nxtLo = bfLoB;
        for (int l = 0; l < L; l++) {
            size_t zo = (size_t)(mlp * 3 + l) * WW;
            mma_layer<<<dim3(HH / 128, MROWS / 128), 256, DSMEM_BYTES>>>(
                (const uint4*)curHi, (const uint4*)curLo,
                (const uint4*)(WtHi + zo), (const uint4*)(WtLo + zo),
                bh[mlp] + (size_t)l * HH, curf, nxtf, nxtHi, nxtLo, l < L - 1 ? 1 : 0);
            float* tf = curf; curf = nxtf; nxtf = tf;
            unsigned* t1 = curHi; curHi = nxtHi; nxtHi = t1;
            unsigned* t2 = curLo; curLo = nxtLo; nxtLo = t2;
        }

        reduce_kernel<<<NA * NB, 256>>>(curf, Wout[mlp], bout[mlp], mask, vec_hat, out, mlp);
    }

    energy_kernel<<<1, 64>>>(out);
}

// round 8
// speedup vs baseline: 2.3805x; 1.0192x over previous
#include <cuda_runtime.h>
#include <cuda_bf16.h>
#include <math.h>

#define NA 128
#define NB 2
#define EE 512
#define HH 1024
#define GG 50
#define MROWS (NA*NA*NB)          // 32768
#define AW ((size_t)MROWS*HH/2)   // u32 words per bf16 activation array
#define WW ((size_t)HH*HH/2)      // u32 words per bf16 weight matrix

// -------- device scratch (no allocations allowed) --------
__device__ float d_hA[(size_t)MROWS*HH];       // final-layer fp32 output
__device__ float d_g[(size_t)MROWS*GG];
__device__ float d_P[NA*NB*HH];
__device__ float d_Q[NA*NB*HH];
__device__ float d_Wg[GG*HH];
__device__ float d_b0[HH];
__device__ float d_eP[NA*NB];
__device__ unsigned d_bfHiA[AW];
__device__ unsigned d_bfLoA[AW];
__device__ unsigned d_bfHiB[AW];
__device__ unsigned d_bfLoB[AW];
__device__ unsigned d_WtHi[6*WW];
__device__ unsigned d_WtLo[6*WW];

__device__ __forceinline__ float gelu_exact(float x) { return x * normcdff(x); }

__device__ __forceinline__ unsigned smem_u32(const void* p) {
    unsigned a;
    asm("{ .reg .u64 t; cvta.to.shared.u64 t, %1; cvt.u32.u64 %0, t; }" : "=r"(a) : "l"(p));
    return a;
}
__device__ __forceinline__ void cp16(unsigned saddr, const void* g) {
    asm volatile("cp.async.cg.shared.global [%0], [%1], 16;" :: "r"(saddr), "l"(g));
}
__device__ __forceinline__ void ldsm4(unsigned addr, unsigned* r) {
    asm volatile("ldmatrix.sync.aligned.m8n8.x4.shared.b16 {%0,%1,%2,%3}, [%4];"
                 : "=r"(r[0]), "=r"(r[1]), "=r"(r[2]), "=r"(r[3]) : "r"(addr));
}
__device__ __forceinline__ void mma16816(float* c, const unsigned* a, unsigned b0, unsigned b1) {
    asm volatile("mma.sync.aligned.m16n8k16.row.col.f32.bf16.bf16.f32 "
                 "{%0,%1,%2,%3}, {%4,%5,%6,%7}, {%8,%9}, {%0,%1,%2,%3};"
                 : "+f"(c[0]), "+f"(c[1]), "+f"(c[2]), "+f"(c[3])
                 : "r"(a[0]), "r"(a[1]), "r"(a[2]), "r"(a[3]), "r"(b0), "r"(b1));
}
__device__ __forceinline__ unsigned pack_hi(float v0, float v1, float& l0, float& l1) {
    __nv_bfloat16 b0 = __float2bfloat16(v0), b1 = __float2bfloat16(v1);
    l0 = v0 - __bfloat162float(b0);
    l1 = v1 - __bfloat162float(b1);
    return ((unsigned)__bfloat16_as_ushort(b1) << 16) | __bfloat16_as_ushort(b0);
}
__device__ __forceinline__ unsigned pack_lo(float l0, float l1) {
    return ((unsigned)__bfloat16_as_ushort(__float2bfloat16(l1)) << 16)
         | __bfloat16_as_ushort(__float2bfloat16(l0));
}
__device__ __forceinline__ float bf_lo(unsigned w) {
    return __bfloat162float(__ushort_as_bfloat16((unsigned short)(w & 0xffffu)));
}
__device__ __forceinline__ float bf_hi(unsigned w) {
    return __bfloat162float(__ushort_as_bfloat16((unsigned short)(w >> 16)));
}

// ================= prologue kernels =================
__global__ void rbf_kernel(const float* __restrict__ dist) {
    int idx = blockIdx.x * blockDim.x + threadIdx.x;
    if (idx >= MROWS * GG) return;
    int m = idx / GG, k = idx - m * GG;
    const float delta = 12.0f / 49.0f;
    const float coeff = -0.5f / (delta * delta);
    float t = dist[m] - delta * (float)k;
    d_g[idx] = expf(coeff * t * t);
}

__global__ void bias0_kernel(const float* __restrict__ Win3,
                             const float* __restrict__ bin,
                             const float* __restrict__ rbf_b) {
    int h = blockIdx.x * blockDim.x + threadIdx.x;
    if (h >= HH) return;
    float s = bin[h];
    for (int e = 0; e < EE; e++) s += rbf_b[e] * Win3[(size_t)e * HH + h];
    d_b0[h] = s;
}

// 64x64-tile fp32 SGEMM for the small precompute GEMMs (more CTAs, better occupancy)
#define SBM 64
#define SBN 64
#define SBK 16
__global__ __launch_bounds__(256)
void sgemm64(const float* __restrict__ A, const float* __restrict__ W,
             float* __restrict__ out, int M, int N, int K)
{
    __shared__ float As[SBK][SBM];
    __shared__ float Bs[SBK][SBN];
    int tid = threadIdx.x;
    int tx = tid & 15, ty = tid >> 4;
    int bm = blockIdx.x * SBM, bn = blockIdx.y * SBN;
    float acc[4][4] = {};
    int arow = tid >> 2, acol = (tid & 3) * 4;
    int brow = tid >> 4, bcol = (tid & 15) * 4;
    for (int k0 = 0; k0 < K; k0 += SBK) {
        float4 va = make_float4(0.f, 0.f, 0.f, 0.f);
        if (bm + arow < M) va = *(const float4*)(A + (size_t)(bm + arow) * K + k0 + acol);
        As[acol + 0][arow] = va.x; As[acol + 1][arow] = va.y;
        As[acol + 2][arow] = va.z; As[acol + 3][arow] = va.w;
        *(float4*)&Bs[brow][bcol] = *(const float4*)(W + (size_t)(k0 + brow) * N + bn + bcol);
        __syncthreads();
        #pragma unroll
        for (int kk = 0; kk < SBK; kk++) {
            float a[4], b[4];
            #pragma unroll
            for (int i = 0; i < 4; i++) a[i] = As[kk][ty * 4 + i];
            #pragma unroll
            for (int j = 0; j < 4; j++) b[j] = Bs[kk][tx * 4 + j];
            #pragma unroll
            for (int i = 0; i < 4; i++)
                #pragma unroll
                for (int j = 0; j < 4; j++)
                    acc[i][j] = fmaf(a[i], b[j], acc[i][j]);
        }
        __syncthreads();
    }
    #pragma unroll
    for (int i = 0; i < 4; i++) {
        int row = bm + ty * 4 + i;
        if (row < M)
            #pragma unroll
            for (int j = 0; j < 4; j++)
                out[(size_t)row * N + bn + tx * 4 + j] = acc[i][j];
    }
}

// h0: write gelu(g@Wg + P + Q + b0) directly as bf16 hi/lo split
__global__ __launch_bounds__(256)
void h0_kernel(unsigned* __restrict__ oHi, unsigned* __restrict__ oLo)
{
    __shared__ float Gs[64][52];
    __shared__ float Ws[52][64];
    int tid = threadIdx.x;
    int bm = blockIdx.x * 64, bn = blockIdx.y * 64;
    for (int idx = tid; idx < 64 * GG; idx += 256) {
        int r = idx / GG, k = idx - r * GG;
        Gs[r][k] = d_g[(size_t)(bm + r) * GG + k];
    }
    for (int idx = tid; idx < GG * 64; idx += 256) {
        int k = idx >> 6, n = idx & 63;
        Ws[k][n] = d_Wg[k * HH + bn + n];
    }
    __syncthreads();
    int tx = tid & 15, ty = tid >> 4;
    float acc[4][4] = {};
    #pragma unroll 10
    for (int k = 0; k < GG; k++) {
        float a[4], b[4];
        #pragma unroll
        for (int i = 0; i < 4; i++) a[i] = Gs[ty * 4 + i][k];
        #pragma unroll
        for (int j = 0; j < 4; j++) b[j] = Ws[k][tx * 4 + j];
        #pragma unroll
        for (int i = 0; i < 4; i++)
            #pragma unroll
            for (int j = 0; j < 4; j++)
                acc[i][j] = fmaf(a[i], b[j], acc[i][j]);
    }
    #pragma unroll
    for (int i = 0; i < 4; i++) {
        int m = bm + ty * 4 + i;
        int bb = m & (NB - 1);
        int jat = (m / NB) & (NA - 1);
        int iat = m / (NB * NA);
        int col0 = bn + tx * 4;
        float v[4];
        #pragma unroll
        for (int j = 0; j < 4; j++) {
            int col = col0 + j;
            float t = acc[i][j] + d_P[(iat * NB + bb) * HH + col]
                    + d_Q[(jat * NB + bb) * HH + col] + d_b0[col];
            v[j] = gelu_exact(t);
        }
        size_t wi = ((size_t)m * HH + col0) >> 1;
        float l0, l1, l2, l3;
        unsigned h0w = pack_hi(v[0], v[1], l0, l1);
        unsigned h1w = pack_hi(v[2], v[3], l2, l3);
        oHi[wi] = h0w; oHi[wi + 1] = h1w;
        oLo[wi] = pack_lo(l0, l1); oLo[wi + 1] = pack_lo(l2, l3);
    }
}

// weight prep: W[K][N] fp32 -> Wt[N][K] bf16 hi/lo (u32 k-pairs)
__global__ __launch_bounds__(256)
void prep_w(const float* __restrict__ We, const float* __restrict__ Wf,
            unsigned* __restrict__ hi, unsigned* __restrict__ lo)
{
    __shared__ float ts[64][33];
    int z = blockIdx.z;
    const float* W = (z < 3) ? We + (size_t)z * HH * HH : Wf + (size_t)(z - 3) * HH * HH;
    int k0 = blockIdx.x * 64, n0 = blockIdx.y * 32;
    int tid = threadIdx.x;
    #pragma unroll
    for (int i = 0; i < 8; i++) {
        int r = (tid >> 5) + i * 8, c = tid & 31;
        ts[r][c] = W[(size_t)(k0 + r) * HH + n0 + c];
    }
    __syncthreads();
    size_t zo = (size_t)z * WW;
    #pragma unroll
    for (int i = 0; i < 4; i++) {
        int on = (tid >> 5) + i * 8;
        int ok = tid & 31;
        float v0 = ts[ok * 2][on], v1 = ts[ok * 2 + 1][on];
        float l0, l1;
        unsigned hw = pack_hi(v0, v1, l0, l1);
        size_t oidx = zo + (size_t)(n0 + on) * (HH / 2) + (k0 >> 1) + ok;
        hi[oidx] = hw;
        lo[oidx] = pack_lo(l0, l1);
    }
}

// ========= bf16x3 mma.sync GEMM layer, double-buffered cp.async =========
// next = res + gelu(A@W^T + bias), res reconstructed from A hi/lo.
// CTA tile 128x128, BK=32, 8 warps (4m x 2n), warp tile 32x64.
#define SMSTR 80                   // 64B data + 16B pad (conflict-free ldmatrix)
#define TILEB (128*SMSTR)          // 10240 B
#define NCHUNK 32
#define DSMEM_BYTES (8*TILEB)      // 81920 (2 buffers x 4 tiles)

__global__ __launch_bounds__(256, 2)
void mma_layer(const uint4* __restrict__ Ah, const uint4* __restrict__ Al,
               const uint4* __restrict__ Bh, const uint4* __restrict__ Bl,
               const float* __restrict__ bias, float* __restrict__ outf,
               unsigned* __restrict__ oHi, unsigned* __restrict__ oLo, int lastLayer)
{
    extern __shared__ char dsm[];
    __shared__ float s_bias[128];
    unsigned base = smem_u32(dsm);

    int tid = threadIdx.x;
    int nt_blk = blockIdx.x, mt_blk = blockIdx.y;
    if (tid < 128) s_bias[tid] = bias[nt_blk * 128 + tid];

    int wid = tid >> 5, lane = tid & 31;
    int wm = wid & 3, wn = wid >> 2;

    float acc[2][8][4];
    #pragma unroll
    for (int i = 0; i < 2; i++)
        #pragma unroll
        for (int j = 0; j < 8; j++)
            #pragma unroll
            for (int k = 0; k < 4; k++) acc[i][j][k] = 0.f;

    const uint4* gAh = Ah + (size_t)(mt_blk * 128) * 128;   // 128 uint4 per row
    const uint4* gAl = Al + (size_t)(mt_blk * 128) * 128;
    const uint4* gBh = Bh + (size_t)(nt_blk * 128) * 128;
    const uint4* gBl = Bl + (size_t)(nt_blk * 128) * 128;

    int ldrow = tid >> 2, ldseg = tid & 3;
    unsigned ldoff = (unsigned)(ldrow * SMSTR + ldseg * 16);
    unsigned ldoff2 = (unsigned)((ldrow + 64) * SMSTR + ldseg * 16);

    // ldmatrix lane addressing
    int g = lane >> 3, lr = lane & 7;
    unsigned aoff0 = (unsigned)((wm * 32 + (g & 1) * 8 + lr) * SMSTR + (g >> 1) * 16);
    unsigned boff0 = (unsigned)((wn * 64 + (g >> 1) * 8 + lr) * SMSTR + (g & 1) * 16);

    // issue chunk 0
    {
        size_t s1 = (size_t)ldrow * 128 + ldseg;
        size_t s2 = (size_t)(ldrow + 64) * 128 + ldseg;
        cp16(base + ldoff, gAh + s1);             cp16(base + ldoff2, gAh + s2);
        cp16(base + TILEB + ldoff, gAl + s1);     cp16(base + TILEB + ldoff2, gAl + s2);
        cp16(base + 2*TILEB + ldoff, gBh + s1);   cp16(base + 2*TILEB + ldoff2, gBh + s2);
        cp16(base + 3*TILEB + ldoff, gBl + s1);   cp16(base + 3*TILEB + ldoff2, gBl + s2);
        asm volatile("cp.async.commit_group;");
    }

    for (int kc = 0; kc < NCHUNK; kc++) {
        int buf = kc & 1;
        if (kc + 1 < NCHUNK) {
            unsigned nb = base + (buf ^ 1) * 4 * TILEB;
            size_t s1 = (size_t)ldrow * 128 + (kc + 1) * 4 + ldseg;
            size_t s2 = (size_t)(ldrow + 64) * 128 + (kc + 1) * 4 + ldseg;
            cp16(nb + ldoff, gAh + s1);             cp16(nb + ldoff2, gAh + s2);
            cp16(nb + TILEB + ldoff, gAl + s1);     cp16(nb + TILEB + ldoff2, gAl + s2);
            cp16(nb + 2*TILEB + ldoff, gBh + s1);   cp16(nb + 2*TILEB + ldoff2, gBh + s2);
            cp16(nb + 3*TILEB + ldoff, gBl + s1);   cp16(nb + 3*TILEB + ldoff2, gBl + s2);
            asm volatile("cp.async.commit_group;");
            asm volatile("cp.async.wait_group 1;");
        } else {
            asm volatile("cp.async.wait_group 0;");
        }
        __syncthreads();

        unsigned bb = base + buf * 4 * TILEB;
        #pragma unroll
        for (int ks = 0; ks < 2; ks++) {
            unsigned kkb = ks * 32;   // 16 bf16 = 32 bytes
            unsigned ah[2][4], al[2][4], b[4][4];
            #pragma unroll
            for (int mt = 0; mt < 2; mt++) {
                unsigned ao = aoff0 + kkb + mt * (16 * SMSTR);
                ldsm4(bb + ao, ah[mt]);
                ldsm4(bb + TILEB + ao, al[mt]);
            }
            #pragma unroll
            for (int p = 0; p < 4; p++)
                ldsm4(bb + 2 * TILEB + boff0 + kkb + p * (16 * SMSTR), b[p]);
            #pragma unroll
            for (int mt = 0; mt < 2; mt++)
                #pragma unroll
                for (int nt = 0; nt < 8; nt++)
                    mma16816(acc[mt][nt], ah[mt], b[nt >> 1][(nt & 1) * 2], b[nt >> 1][(nt & 1) * 2 + 1]);
            #pragma unroll
            for (int mt = 0; mt < 2; mt++)
                #pragma unroll
                for (int nt = 0; nt < 8; nt++)
                    mma16816(acc[mt][nt], al[mt], b[nt >> 1][(nt & 1) * 2], b[nt >> 1][(nt & 1) * 2 + 1]);
            #pragma unroll
            for (int p = 0; p < 4; p++)
                ldsm4(bb + 3 * TILEB + boff0 + kkb + p * (16 * SMSTR), b[p]);
            #pragma unroll
            for (int mt = 0; mt < 2; mt++)
                #pragma unroll
                for (int nt = 0; nt < 8; nt++)
                    mma16816(acc[mt][nt], ah[mt], b[nt >> 1][(nt & 1) * 2], b[nt >> 1][(nt & 1) * 2 + 1]);
        }
        __syncthreads();
    }

    // epilogue: res reconstructed from A hi/lo at the output columns
    const unsigned* rAh = (const unsigned*)Ah;
    const unsigned* rAl = (const unsigned*)Al;
    #pragma unroll
    for (int mt = 0; mt < 2; mt++) {
        #pragma unroll
        for (int half = 0; half < 2; half++) {
            int row = mt_blk * 128 + wm * 32 + mt * 16 + half * 8 + (lane >> 2);
            #pragma unroll
            for (int nt = 0; nt < 8; nt++) {
                int cl = wn * 64 + nt * 8 + (lane & 3) * 2;
                size_t gi = (size_t)row * HH + nt_blk * 128 + cl;
                size_t wi = gi >> 1;
                unsigned hw = rAh[wi], lw = rAl[wi];
                float r0 = bf_lo(hw) + bf_lo(lw);
                float r1 = bf_hi(hw) + bf_hi(lw);
                float v0 = r0 + gelu_exact(acc[mt][nt][half * 2 + 0] + s_bias[cl]);
                float v1 = r1 + gelu_exact(acc[mt][nt][half * 2 + 1] + s_bias[cl + 1]);
                if (lastLayer) {
                    *(float2*)(outf + gi) = make_float2(v0, v1);
                } else {
                    float l0, l1;
                    unsigned ohw = pack_hi(v0, v1, l0, l1);
                    oHi[wi] = ohw;
                    oLo[wi] = pack_lo(l0, l1);
                }
            }
        }
    }
}

// ========= reductions (fp32, deterministic) =========
__global__ __launch_bounds__(256)
void reduce_kernel(const float* __restrict__ h, const float* __restrict__ Wout,
                   const float* __restrict__ bout, const int* __restrict__ mask,
                   const float* __restrict__ vec_hat, float* __restrict__ out, int mode)
{
    __shared__ float sW[HH];
    __shared__ float sred[8][4];
    int tid = threadIdx.x;
    int jb = blockIdx.x;
    int j = jb / NB, b = jb % NB;
    for (int c = tid; c < HH; c += 256) sW[c] = Wout[c];
    __syncthreads();
    int warp = tid >> 5, lane = tid & 31;
    float eacc = 0.f, fx = 0.f, fy = 0.f, fz = 0.f;
    float bo = bout[0];
    bool mj = mask[b * NA + j] != 0;
    for (int i = warp; i < NA; i += 8) {
        size_t m = ((size_t)(i * NA + j)) * NB + b;
        const float* hr = h + m * HH;
        float s = 0.f;
        for (int c = lane; c < HH; c += 32) s += hr[c] * sW[c];
        #pragma unroll
        for (int o = 16; o > 0; o >>= 1) s += __shfl_xor_sync(0xffffffffu, s, o);
        if (lane == 0) {
            float entry = (mj && mask[b * NA + i] != 0) ? 1.0f : 0.0f;
            float val = (s + bo) * entry;
            if (mode == 0) eacc += val;
            else {
                const float* v = vec_hat + m * 3;
                fx += val * v[0]; fy += val * v[1]; fz += val * v[2];
            }
        }
    }
    if (lane == 0) { sred[warp][0] = eacc; sred[warp][1] = fx; sred[warp][2] = fy; sred[warp][3] = fz; }
    __syncthreads();
    if (tid == 0) {
        float a0 = 0, a1 = 0, a2 = 0, a3 = 0;
        for (int w = 0; w < 8; w++) { a0 += sred[w][0]; a1 += sred[w][1]; a2 += sred[w][2]; a3 += sred[w][3]; }
        if (mode == 0) d_eP[jb] = a0;
        else {
            int o = 2 + (b * NA + j) * 3;
            out[o + 0] = a1 / 60.0f; out[o + 1] = a2 / 60.0f; out[o + 2] = a3 / 60.0f;
        }
    }
}

__global__ void energy_kernel(float* __restrict__ out) {
    int tid = threadIdx.x;
    int b = tid >> 5, lane = tid & 31;
    if (b >= NB) return;
    float s = 0.f;
    for (int j = lane; j < NA; j += 32) s += d_eP[j * NB + b];
    #pragma unroll
    for (int o = 16; o > 0; o >>= 1) s += __shfl_xor_sync(0xffffffffu, s, o);
    if (lane == 0) out[b] = s / 3600.0f;
}

// ========= launch =========
extern "C" void kernel_launch(void* const* d_in, const int* in_sizes, int n_in,
                              void* d_out, int out_size)
{
    const float* x       = (const float*)d_in[0];
    const float* dist    = (const float*)d_in[1];
    const float* vec_hat = (const float*)d_in[2];
    const int*   mask    = (const int*)d_in[3];   // bool promoted to int32
    const float* rbf_W   = (const float*)d_in[4];
    const float* rbf_b   = (const float*)d_in[5];
    const float* Win[2]  = {(const float*)d_in[6],  (const float*)d_in[12]};
    const float* bin[2]  = {(const float*)d_in[7],  (const float*)d_in[13]};
    const float* Wh[2]   = {(const float*)d_in[8],  (const float*)d_in[14]};
    const float* bh[2]   = {(const float*)d_in[9],  (const float*)d_in[15]};
    const float* Wout[2] = {(const float*)d_in[10], (const float*)d_in[16]};
    const float* bout[2] = {(const float*)d_in[11], (const float*)d_in[17]};
    int L = in_sizes[8] / (HH * HH);
    float* out = (float*)d_out;

    static int attr_set = 0;
    if (!attr_set) {
        cudaFuncSetAttribute(mma_layer, cudaFuncAttributeMaxDynamicSharedMemorySize, DSMEM_BYTES);
        attr_set = 1;
    }

    float *hA, *P, *Q, *Wg;
    unsigned *bfHiA, *bfLoA, *bfHiB, *bfLoB, *WtHi, *WtLo;
    cudaGetSymbolAddress((void**)&hA, d_hA);
    cudaGetSymbolAddress((void**)&P,  d_P);
    cudaGetSymbolAddress((void**)&Q,  d_Q);
    cudaGetSymbolAddress((void**)&Wg, d_Wg);
    cudaGetSymbolAddress((void**)&bfHiA, d_bfHiA);
    cudaGetSymbolAddress((void**)&bfLoA, d_bfLoA);
    cudaGetSymbolAddress((void**)&bfHiB, d_bfHiB);
    cudaGetSymbolAddress((void**)&bfLoB, d_bfLoB);
    cudaGetSymbolAddress((void**)&WtHi, d_WtHi);
    cudaGetSymbolAddress((void**)&WtLo, d_WtLo);

    rbf_kernel<<<(MROWS * GG + 255) / 256, 256>>>(dist);
    prep_w<<<dim3(16, 32, 6), 256>>>(Wh[0], Wh[1], WtHi, WtLo);

    for (int mlp = 0; mlp < 2; mlp++) {
        const float* W1 = Win[mlp];
        const float* W2 = Win[mlp] + (size_t)EE * HH;
        const float* W3 = Win[mlp] + (size_t)2 * EE * HH;

        sgemm64<<<dim3(4, 16), 256>>>(x, W1, P, NA * NB, HH, EE);
        sgemm64<<<dim3(4, 16), 256>>>(x, W2, Q, NA * NB, HH, EE);
        sgemm64<<<dim3(1, 16), 256>>>(rbf_W, W3, Wg, GG, HH, EE);
        bias0_kernel<<<4, 256>>>(W3, bin[mlp], rbf_b);

        h0_kernel<<<dim3(MROWS / 64, HH / 64), 256>>>(bfHiA, bfLoA);

        unsigned* curHi = bfHiA; unsigned* curLo = bfLoA;
        unsigned* nxtHi = bfHiB; unsigned* nxtLo = bfLoB;
        for (int l = 0; l < L; l++) {
            size_t zo = (size_t)(mlp * 3 + l) * WW;
            int last = (l == L - 1) ? 1 : 0;
            mma_layer<<<dim3(HH / 128, MROWS / 128), 256, DSMEM_BYTES>>>(
                (const uint4*)curHi, (const uint4*)curLo,
                (const uint4*)(WtHi + zo), (const uint4*)(WtLo + zo),
                bh[mlp] + (size_t)l * HH, hA, nxtHi, nxtLo, last);
            unsigned* t1 = curHi; curHi = nxtHi; nxtHi = t1;
            unsigned* t2 = curLo; curLo = nxtLo; nxtLo = t2;
        }

        reduce_kernel<<<NA * NB, 256>>>(hA, Wout[mlp], bout[mlp], mask, vec_hat, out, mlp);
    }

    energy_kernel<<<1, 64>>>(out);
}

// round 9
// speedup vs baseline: 3.0824x; 1.2949x over previous
#include <cuda_runtime.h>
#include <cuda_fp16.h>
#include <math.h>

#define NA 128
#define NB 2
#define EE 512
#define HH 1024
#define GG 50
#define MROWS (NA*NA*NB)          // 32768
#define AW ((size_t)MROWS*HH/2)   // u32 words per fp16 activation array
#define WW ((size_t)HH*HH/2)      // u32 words per fp16 weight matrix

// -------- device scratch (no allocations allowed) --------
__device__ float d_hA[(size_t)MROWS*HH];       // final-layer fp32 output
__device__ float d_g[(size_t)MROWS*GG];
__device__ float d_P[NA*NB*HH];
__device__ float d_Q[NA*NB*HH];
__device__ float d_Wg[GG*HH];
__device__ float d_b0[HH];
__device__ float d_eP[NA*NB];
__device__ unsigned d_fHiA[AW];
__device__ unsigned d_fLoA[AW];
__device__ unsigned d_fHiB[AW];
__device__ unsigned d_fLoB[AW];
__device__ unsigned d_Wt[6*WW];

__device__ __forceinline__ float gelu_exact(float x) { return x * normcdff(x); }

__device__ __forceinline__ unsigned smem_u32(const void* p) {
    unsigned a;
    asm("{ .reg .u64 t; cvta.to.shared.u64 t, %1; cvt.u32.u64 %0, t; }" : "=r"(a) : "l"(p));
    return a;
}
__device__ __forceinline__ void cp16(unsigned saddr, const void* g) {
    asm volatile("cp.async.cg.shared.global [%0], [%1], 16;" :: "r"(saddr), "l"(g));
}
__device__ __forceinline__ void ldsm4(unsigned addr, unsigned* r) {
    asm volatile("ldmatrix.sync.aligned.m8n8.x4.shared.b16 {%0,%1,%2,%3}, [%4];"
                 : "=r"(r[0]), "=r"(r[1]), "=r"(r[2]), "=r"(r[3]) : "r"(addr));
}
__device__ __forceinline__ void mma16816(float* c, const unsigned* a, unsigned b0, unsigned b1) {
    asm volatile("mma.sync.aligned.m16n8k16.row.col.f32.f16.f16.f32 "
                 "{%0,%1,%2,%3}, {%4,%5,%6,%7}, {%8,%9}, {%0,%1,%2,%3};"
                 : "+f"(c[0]), "+f"(c[1]), "+f"(c[2]), "+f"(c[3])
                 : "r"(a[0]), "r"(a[1]), "r"(a[2]), "r"(a[3]), "r"(b0), "r"(b1));
}
__device__ __forceinline__ unsigned pack_hi(float v0, float v1, float& l0, float& l1) {
    __half a = __float2half_rn(v0), b = __float2half_rn(v1);
    l0 = v0 - __half2float(a);
    l1 = v1 - __half2float(b);
    return ((unsigned)__half_as_ushort(b) << 16) | __half_as_ushort(a);
}
__device__ __forceinline__ unsigned pack_lo(float l0, float l1) {
    return ((unsigned)__half_as_ushort(__float2half_rn(l1)) << 16)
         | __half_as_ushort(__float2half_rn(l0));
}
__device__ __forceinline__ unsigned pack_h(float v0, float v1) {
    return ((unsigned)__half_as_ushort(__float2half_rn(v1)) << 16)
         | __half_as_ushort(__float2half_rn(v0));
}
__device__ __forceinline__ float hf_lo(unsigned w) {
    return __half2float(__ushort_as_half((unsigned short)(w & 0xffffu)));
}
__device__ __forceinline__ float hf_hi(unsigned w) {
    return __half2float(__ushort_as_half((unsigned short)(w >> 16)));
}

// ================= prologue kernels =================
__global__ void rbf_kernel(const float* __restrict__ dist) {
    int idx = blockIdx.x * blockDim.x + threadIdx.x;
    if (idx >= MROWS * GG) return;
    int m = idx / GG, k = idx - m * GG;
    const float delta = 12.0f / 49.0f;
    const float coeff = -0.5f / (delta * delta);
    float t = dist[m] - delta * (float)k;
    d_g[idx] = expf(coeff * t * t);
}

__global__ void bias0_kernel(const float* __restrict__ Win3,
                             const float* __restrict__ bin,
                             const float* __restrict__ rbf_b) {
    int h = blockIdx.x * blockDim.x + threadIdx.x;
    if (h >= HH) return;
    float s = bin[h];
    for (int e = 0; e < EE; e++) s += rbf_b[e] * Win3[(size_t)e * HH + h];
    d_b0[h] = s;
}

#define SBM 64
#define SBN 64
#define SBK 16
__global__ __launch_bounds__(256)
void sgemm64(const float* __restrict__ A, const float* __restrict__ W,
             float* __restrict__ out, int M, int N, int K)
{
    __shared__ float As[SBK][SBM];
    __shared__ float Bs[SBK][SBN];
    int tid = threadIdx.x;
    int tx = tid & 15, ty = tid >> 4;
    int bm = blockIdx.x * SBM, bn = blockIdx.y * SBN;
    float acc[4][4] = {};
    int arow = tid >> 2, acol = (tid & 3) * 4;
    int brow = tid >> 4, bcol = (tid & 15) * 4;
    for (int k0 = 0; k0 < K; k0 += SBK) {
        float4 va = make_float4(0.f, 0.f, 0.f, 0.f);
        if (bm + arow < M) va = *(const float4*)(A + (size_t)(bm + arow) * K + k0 + acol);
        As[acol + 0][arow] = va.x; As[acol + 1][arow] = va.y;
        As[acol + 2][arow] = va.z; As[acol + 3][arow] = va.w;
        *(float4*)&Bs[brow][bcol] = *(const float4*)(W + (size_t)(k0 + brow) * N + bn + bcol);
        __syncthreads();
        #pragma unroll
        for (int kk = 0; kk < SBK; kk++) {
            float a[4], b[4];
            #pragma unroll
            for (int i = 0; i < 4; i++) a[i] = As[kk][ty * 4 + i];
            #pragma unroll
            for (int j = 0; j < 4; j++) b[j] = Bs[kk][tx * 4 + j];
            #pragma unroll
            for (int i = 0; i < 4; i++)
                #pragma unroll
                for (int j = 0; j < 4; j++)
                    acc[i][j] = fmaf(a[i], b[j], acc[i][j]);
        }
        __syncthreads();
    }
    #pragma unroll
    for (int i = 0; i < 4; i++) {
        int row = bm + ty * 4 + i;
        if (row < M)
            #pragma unroll
            for (int j = 0; j < 4; j++)
                out[(size_t)row * N + bn + tx * 4 + j] = acc[i][j];
    }
}

// h0: write gelu(g@Wg + P + Q + b0) directly as fp16 hi/lo split
__global__ __launch_bounds__(256)
void h0_kernel(unsigned* __restrict__ oHi, unsigned* __restrict__ oLo)
{
    __shared__ float Gs[64][52];
    __shared__ float Ws[52][64];
    int tid = threadIdx.x;
    int bm = blockIdx.x * 64, bn = blockIdx.y * 64;
    for (int idx = tid; idx < 64 * GG; idx += 256) {
        int r = idx / GG, k = idx - r * GG;
        Gs[r][k] = d_g[(size_t)(bm + r) * GG + k];
    }
    for (int idx = tid; idx < GG * 64; idx += 256) {
        int k = idx >> 6, n = idx & 63;
        Ws[k][n] = d_Wg[k * HH + bn + n];
    }
    __syncthreads();
    int tx = tid & 15, ty = tid >> 4;
    float acc[4][4] = {};
    #pragma unroll 10
    for (int k = 0; k < GG; k++) {
        float a[4], b[4];
        #pragma unroll
        for (int i = 0; i < 4; i++) a[i] = Gs[ty * 4 + i][k];
        #pragma unroll
        for (int j = 0; j < 4; j++) b[j] = Ws[k][tx * 4 + j];
        #pragma unroll
        for (int i = 0; i < 4; i++)
            #pragma unroll
            for (int j = 0; j < 4; j++)
                acc[i][j] = fmaf(a[i], b[j], acc[i][j]);
    }
    #pragma unroll
    for (int i = 0; i < 4; i++) {
        int m = bm + ty * 4 + i;
        int bb = m & (NB - 1);
        int jat = (m / NB) & (NA - 1);
        int iat = m / (NB * NA);
        int col0 = bn + tx * 4;
        float v[4];
        #pragma unroll
        for (int j = 0; j < 4; j++) {
            int col = col0 + j;
            float t = acc[i][j] + d_P[(iat * NB + bb) * HH + col]
                    + d_Q[(jat * NB + bb) * HH + col] + d_b0[col];
            v[j] = gelu_exact(t);
        }
        size_t wi = ((size_t)m * HH + col0) >> 1;
        float l0, l1, l2, l3;
        unsigned h0w = pack_hi(v[0], v[1], l0, l1);
        unsigned h1w = pack_hi(v[2], v[3], l2, l3);
        oHi[wi] = h0w; oHi[wi + 1] = h1w;
        oLo[wi] = pack_lo(l0, l1); oLo[wi + 1] = pack_lo(l2, l3);
    }
}

// weight prep: W[K][N] fp32 -> Wt[N][K] single fp16 (u32 k-pairs)
__global__ __launch_bounds__(256)
void prep_w(const float* __restrict__ We, const float* __restrict__ Wf,
            unsigned* __restrict__ wt)
{
    __shared__ float ts[64][33];
    int z = blockIdx.z;
    const float* W = (z < 3) ? We + (size_t)z * HH * HH : Wf + (size_t)(z - 3) * HH * HH;
    int k0 = blockIdx.x * 64, n0 = blockIdx.y * 32;
    int tid = threadIdx.x;
    #pragma unroll
    for (int i = 0; i < 8; i++) {
        int r = (tid >> 5) + i * 8, c = tid & 31;
        ts[r][c] = W[(size_t)(k0 + r) * HH + n0 + c];
    }
    __syncthreads();
    size_t zo = (size_t)z * WW;
    #pragma unroll
    for (int i = 0; i < 4; i++) {
        int on = (tid >> 5) + i * 8;
        int ok = tid & 31;
        float v0 = ts[ok * 2][on], v1 = ts[ok * 2 + 1][on];
        size_t oidx = zo + (size_t)(n0 + on) * (HH / 2) + (k0 >> 1) + ok;
        wt[oidx] = pack_h(v0, v1);
    }
}

// ========= fp16 2-pass mma.sync GEMM layer, 3-stage cp.async pipeline =========
// next = res + gelu((Ah+Al)@W^T + bias); res reconstructed from Ah/Al.
// CTA tile 128x128, BK=32, 8 warps (4m x 2n), warp tile 32x64.
#define SMSTR 80                   // 64B data + 16B pad (conflict-free ldmatrix)
#define TILEB (128*SMSTR)          // 10240 B
#define NCHUNK 32
#define NSTAGE 3
#define STAGEB (3*TILEB)           // Ah, Al, B per stage
#define DSMEM_BYTES (NSTAGE*STAGEB)  // 92160

__global__ __launch_bounds__(256, 2)
void mma_layer(const uint4* __restrict__ Ah, const uint4* __restrict__ Al,
               const uint4* __restrict__ Bw,
               const float* __restrict__ bias, float* __restrict__ outf,
               unsigned* __restrict__ oHi, unsigned* __restrict__ oLo, int lastLayer)
{
    extern __shared__ char dsm[];
    __shared__ float s_bias[128];
    unsigned base = smem_u32(dsm);

    int tid = threadIdx.x;
    int nt_blk = blockIdx.x, mt_blk = blockIdx.y;
    if (tid < 128) s_bias[tid] = bias[nt_blk * 128 + tid];

    int wid = tid >> 5, lane = tid & 31;
    int wm = wid & 3, wn = wid >> 2;

    float acc[2][8][4];
    #pragma unroll
    for (int i = 0; i < 2; i++)
        #pragma unroll
        for (int j = 0; j < 8; j++)
            #pragma unroll
            for (int k = 0; k < 4; k++) acc[i][j][k] = 0.f;

    const uint4* gAh = Ah + (size_t)(mt_blk * 128) * 128;   // 128 uint4 per row
    const uint4* gAl = Al + (size_t)(mt_blk * 128) * 128;
    const uint4* gB  = Bw + (size_t)(nt_blk * 128) * 128;

    int ldrow = tid >> 2, ldseg = tid & 3;
    unsigned ldoff = (unsigned)(ldrow * SMSTR + ldseg * 16);
    unsigned ldoff2 = (unsigned)((ldrow + 64) * SMSTR + ldseg * 16);

    // ldmatrix lane addressing
    int g = lane >> 3, lr = lane & 7;
    unsigned aoff0 = (unsigned)((wm * 32 + (g & 1) * 8 + lr) * SMSTR + (g >> 1) * 16);
    unsigned boff0 = (unsigned)((wn * 64 + (g >> 1) * 8 + lr) * SMSTR + (g & 1) * 16);

    // issue chunks 0 and 1
    #pragma unroll
    for (int pc = 0; pc < 2; pc++) {
        unsigned sb = base + pc * STAGEB;
        size_t s1 = (size_t)ldrow * 128 + pc * 4 + ldseg;
        size_t s2 = (size_t)(ldrow + 64) * 128 + pc * 4 + ldseg;
        cp16(sb + ldoff, gAh + s1);             cp16(sb + ldoff2, gAh + s2);
        cp16(sb + TILEB + ldoff, gAl + s1);     cp16(sb + TILEB + ldoff2, gAl + s2);
        cp16(sb + 2*TILEB + ldoff, gB + s1);    cp16(sb + 2*TILEB + ldoff2, gB + s2);
        asm volatile("cp.async.commit_group;");
    }

    int stage = 0;
    for (int kc = 0; kc < NCHUNK; kc++) {
        if (kc + 2 < NCHUNK) {
            int ps = (stage + 2) % NSTAGE;
            unsigned sb = base + ps * STAGEB;
            size_t s1 = (size_t)ldrow * 128 + (kc + 2) * 4 + ldseg;
            size_t s2 = (size_t)(ldrow + 64) * 128 + (kc + 2) * 4 + ldseg;
            cp16(sb + ldoff, gAh + s1);             cp16(sb + ldoff2, gAh + s2);
            cp16(sb + TILEB + ldoff, gAl + s1);     cp16(sb + TILEB + ldoff2, gAl + s2);
            cp16(sb + 2*TILEB + ldoff, gB + s1);    cp16(sb + 2*TILEB + ldoff2, gB + s2);
            asm volatile("cp.async.commit_group;");
            asm volatile("cp.async.wait_group 2;");
        } else if (kc + 1 < NCHUNK) {
            asm volatile("cp.async.wait_group 1;");
        } else {
            asm volatile("cp.async.wait_group 0;");
        }
        __syncthreads();

        unsigned bb = base + stage * STAGEB;
        #pragma unroll
        for (int ks = 0; ks < 2; ks++) {
            unsigned kkb = ks * 32;   // 16 fp16 = 32 bytes
            unsigned ah[2][4], al[2][4], b[4][4];
            #pragma unroll
            for (int mt = 0; mt < 2; mt++) {
                unsigned ao = aoff0 + kkb + mt * (16 * SMSTR);
                ldsm4(bb + ao, ah[mt]);
                ldsm4(bb + TILEB + ao, al[mt]);
            }
            #pragma unroll
            for (int p = 0; p < 4; p++)
                ldsm4(bb + 2 * TILEB + boff0 + kkb + p * (16 * SMSTR), b[p]);
            #pragma unroll
            for (int mt = 0; mt < 2; mt++)
                #pragma unroll
                for (int nt = 0; nt < 8; nt++)
                    mma16816(acc[mt][nt], ah[mt], b[nt >> 1][(nt & 1) * 2], b[nt >> 1][(nt & 1) * 2 + 1]);
            #pragma unroll
            for (int mt = 0; mt < 2; mt++)
                #pragma unroll
                for (int nt = 0; nt < 8; nt++)
                    mma16816(acc[mt][nt], al[mt], b[nt >> 1][(nt & 1) * 2], b[nt >> 1][(nt & 1) * 2 + 1]);
        }
        __syncthreads();
        stage = (stage + 1) % NSTAGE;
    }

    // epilogue: res reconstructed from A hi/lo at the output columns
    const unsigned* rAh = (const unsigned*)Ah;
    const unsigned* rAl = (const unsigned*)Al;
    #pragma unroll
    for (int mt = 0; mt < 2; mt++) {
        #pragma unroll
        for (int half = 0; half < 2; half++) {
            int row = mt_blk * 128 + wm * 32 + mt * 16 + half * 8 + (lane >> 2);
            #pragma unroll
            for (int nt = 0; nt < 8; nt++) {
                int cl = wn * 64 + nt * 8 + (lane & 3) * 2;
                size_t gi = (size_t)row * HH + nt_blk * 128 + cl;
                size_t wi = gi >> 1;
                unsigned hw = rAh[wi], lw = rAl[wi];
                float r0 = hf_lo(hw) + hf_lo(lw);
                float r1 = hf_hi(hw) + hf_hi(lw);
                float v0 = r0 + gelu_exact(acc[mt][nt][half * 2 + 0] + s_bias[cl]);
                float v1 = r1 + gelu_exact(acc[mt][nt][half * 2 + 1] + s_bias[cl + 1]);
                if (lastLayer) {
                    *(float2*)(outf + gi) = make_float2(v0, v1);
                } else {
                    float l0, l1;
                    unsigned ohw = pack_hi(v0, v1, l0, l1);
                    oHi[wi] = ohw;
                    oLo[wi] = pack_lo(l0, l1);
                }
            }
        }
    }
}

// ========= reductions (fp32, deterministic) =========
__global__ __launch_bounds__(256)
void reduce_kernel(const float* __restrict__ h, const float* __restrict__ Wout,
                   const float* __restrict__ bout, const int* __restrict__ mask,
                   const float* __restrict__ vec_hat, float* __restrict__ out, int mode)
{
    __shared__ float sW[HH];
    __shared__ float sred[8][4];
    int tid = threadIdx.x;
    int jb = blockIdx.x;
    int j = jb / NB, b = jb % NB;
    for (int c = tid; c < HH; c += 256) sW[c] = Wout[c];
    __syncthreads();
    int warp = tid >> 5, lane = tid & 31;
    float eacc = 0.f, fx = 0.f, fy = 0.f, fz = 0.f;
    float bo = bout[0];
    bool mj = mask[b * NA + j] != 0;
    for (int i = warp; i < NA; i += 8) {
        size_t m = ((size_t)(i * NA + j)) * NB + b;
        const float* hr = h + m * HH;
        float s = 0.f;
        for (int c = lane; c < HH; c += 32) s += hr[c] * sW[c];
        #pragma unroll
        for (int o = 16; o > 0; o >>= 1) s += __shfl_xor_sync(0xffffffffu, s, o);
        if (lane == 0) {
            float entry = (mj && mask[b * NA + i] != 0) ? 1.0f : 0.0f;
            float val = (s + bo) * entry;
            if (mode == 0) eacc += val;
            else {
                const float* v = vec_hat + m * 3;
                fx += val * v[0]; fy += val * v[1]; fz += val * v[2];
            }
        }
    }
    if (lane == 0) { sred[warp][0] = eacc; sred[warp][1] = fx; sred[warp][2] = fy; sred[warp][3] = fz; }
    __syncthreads();
    if (tid == 0) {
        float a0 = 0, a1 = 0, a2 = 0, a3 = 0;
        for (int w = 0; w < 8; w++) { a0 += sred[w][0]; a1 += sred[w][1]; a2 += sred[w][2]; a3 += sred[w][3]; }
        if (mode == 0) d_eP[jb] = a0;
        else {
            int o = 2 + (b * NA + j) * 3;
            out[o + 0] = a1 / 60.0f; out[o + 1] = a2 / 60.0f; out[o + 2] = a3 / 60.0f;
        }
    }
}

__global__ void energy_kernel(float* __restrict__ out) {
    int tid = threadIdx.x;
    int b = tid >> 5, lane = tid & 31;
    if (b >= NB) return;
    float s = 0.f;
    for (int j = lane; j < NA; j += 32) s += d_eP[j * NB + b];
    #pragma unroll
    for (int o = 16; o > 0; o >>= 1) s += __shfl_xor_sync(0xffffffffu, s, o);
    if (lane == 0) out[b] = s / 3600.0f;
}

// ========= launch =========
extern "C" void kernel_launch(void* const* d_in, const int* in_sizes, int n_in,
                              void* d_out, int out_size)
{
    const float* x       = (const float*)d_in[0];
    const float* dist    = (const float*)d_in[1];
    const float* vec_hat = (const float*)d_in[2];
    const int*   mask    = (const int*)d_in[3];   // bool promoted to int32
    const float* rbf_W   = (const float*)d_in[4];
    const float* rbf_b   = (const float*)d_in[5];
    const float* Win[2]  = {(const float*)d_in[6],  (const float*)d_in[12]};
    const float* bin[2]  = {(const float*)d_in[7],  (const float*)d_in[13]};
    const float* Wh[2]   = {(const float*)d_in[8],  (const float*)d_in[14]};
    const float* bh[2]   = {(const float*)d_in[9],  (const float*)d_in[15]};
    const float* Wout[2] = {(const float*)d_in[10], (const float*)d_in[16]};
    const float* bout[2] = {(const float*)d_in[11], (const float*)d_in[17]};
    int L = in_sizes[8] / (HH * HH);
    float* out = (float*)d_out;

    static int attr_set = 0;
    if (!attr_set) {
        cudaFuncSetAttribute(mma_layer, cudaFuncAttributeMaxDynamicSharedMemorySize, DSMEM_BYTES);
        attr_set = 1;
    }

    float *hA, *P, *Q, *Wg;
    unsigned *fHiA, *fLoA, *fHiB, *fLoB, *Wt;
    cudaGetSymbolAddress((void**)&hA, d_hA);
    cudaGetSymbolAddress((void**)&P,  d_P);
    cudaGetSymbolAddress((void**)&Q,  d_Q);
    cudaGetSymbolAddress((void**)&Wg, d_Wg);
    cudaGetSymbolAddress((void**)&fHiA, d_fHiA);
    cudaGetSymbolAddress((void**)&fLoA, d_fLoA);
    cudaGetSymbolAddress((void**)&fHiB, d_fHiB);
    cudaGetSymbolAddress((void**)&fLoB, d_fLoB);
    cudaGetSymbolAddress((void**)&Wt, d_Wt);

    rbf_kernel<<<(MROWS * GG + 255) / 256, 256>>>(dist);
    prep_w<<<dim3(16, 32, 6), 256>>>(Wh[0], Wh[1], Wt);

    for (int mlp = 0; mlp < 2; mlp++) {
        const float* W1 = Win[mlp];
        const float* W2 = Win[mlp] + (size_t)EE * HH;
        const float* W3 = Win[mlp] + (size_t)2 * EE * HH;

        sgemm64<<<dim3(4, 16), 256>>>(x, W1, P, NA * NB, HH, EE);
        sgemm64<<<dim3(4, 16), 256>>>(x, W2, Q, NA * NB, HH, EE);
        sgemm64<<<dim3(1, 16), 256>>>(rbf_W, W3, Wg, GG, HH, EE);
        bias0_kernel<<<4, 256>>>(W3, bin[mlp], rbf_b);

        h0_kernel<<<dim3(MROWS / 64, HH / 64), 256>>>(fHiA, fLoA);

        unsigned* curHi = fHiA; unsigned* curLo = fLoA;
        unsigned* nxtHi = fHiB; unsigned* nxtLo = fLoB;
        for (int l = 0; l < L; l++) {
            size_t zo = (size_t)(mlp * 3 + l) * WW;
            int last = (l == L - 1) ? 1 : 0;
            mma_layer<<<dim3(HH / 128, MROWS / 128), 256, DSMEM_BYTES>>>(
                (const uint4*)curHi, (const uint4*)curLo,
                (const uint4*)(Wt + zo),
                bh[mlp] + (size_t)l * HH, hA, nxtHi, nxtLo, last);
            unsigned* t1 = curHi; curHi = nxtHi; nxtHi = t1;
            unsigned* t2 = curLo; curLo = nxtLo; nxtLo = t2;
        }

        reduce_kernel<<<NA * NB, 256>>>(hA, Wout[mlp], bout[mlp], mask, vec_hat, out, mlp);
    }

    energy_kernel<<<1, 64>>>(out);
}